// round 13
// baseline (speedup 1.0000x reference)
#include <cuda_runtime.h>
#include <math.h>
#include <stdint.h>

#define IN_F  2048
#define OUT_F 2048
#define NROWS 8192   // 4 * 2048

// ---------------------------------------------------------------------------
// Scratch (__device__ globals; no runtime allocation allowed)
// int8 fixed-point splits, power-of-two scales:
//   x  ~= x0*2^-4  + x1*2^-12
//   k  ~= k0*2^-12 + k1*2^-20
//   mu ~= m0*2^-12 + m1*2^-20
// ---------------------------------------------------------------------------
__device__ __align__(16) int8_t g_x0[(size_t)NROWS * IN_F];
__device__ __align__(16) int8_t g_x1[(size_t)NROWS * IN_F];
__device__ __align__(16) int8_t g_k0[(size_t)OUT_F * IN_F];
__device__ __align__(16) int8_t g_k1[(size_t)OUT_F * IN_F];
__device__ __align__(16) int8_t g_m0[(size_t)OUT_F * IN_F];
__device__ __align__(16) int8_t g_m1[(size_t)OUT_F * IN_F];
__device__ float g_knorm[OUT_F];
__device__ float g_xnorm[NROWS];

__device__ __forceinline__ float softplus_f(float x) {
    return fmaxf(x, 0.0f) + log1pf(expf(-fabsf(x)));
}

__device__ __forceinline__ int q8(float v) {
    int r = __float2int_rn(v);
    return r > 127 ? 127 : (r < -127 ? -127 : r);
}
__device__ __forceinline__ uint32_t pack4(int a, int b, int c, int d) {
    return (a & 0xff) | ((b & 0xff) << 8) | ((c & 0xff) << 16) | ((d & 0xff) << 24);
}

__device__ __forceinline__ void cp16(uint32_t sa, const void* gp) {
    asm volatile("cp.async.cg.shared.global [%0], [%1], 16;"
                 :: "r"(sa), "l"(__cvta_generic_to_global(gp)) : "memory");
}
#define CP_COMMIT() asm volatile("cp.async.commit_group;" ::: "memory")
#define CP_WAIT1()  asm volatile("cp.async.wait_group 1;" ::: "memory")
#define CP_WAIT0()  asm volatile("cp.async.wait_group 0;" ::: "memory")

__device__ __forceinline__ uint32_t smem_u32(const void* p) {
    uint32_t a;
    asm("{ .reg .u64 t; cvta.to.shared.u64 t, %1; cvt.u32.u64 %0, t; }" : "=r"(a) : "l"(p));
    return a;
}

__device__ __forceinline__ void ldsm_x4(uint32_t* r, uint32_t addr) {
    asm volatile("ldmatrix.sync.aligned.m8n8.x4.shared.b16 {%0,%1,%2,%3}, [%4];"
                 : "=r"(r[0]), "=r"(r[1]), "=r"(r[2]), "=r"(r[3]) : "r"(addr));
}

// int8 MMA: m16n8k32, s32 accumulate
__device__ __forceinline__ void mma_s8(int* d, const uint32_t* a, const uint32_t* b) {
    asm volatile("mma.sync.aligned.m16n8k32.row.col.s32.s8.s8.s32 "
                 "{%0,%1,%2,%3}, {%4,%5,%6,%7}, {%8,%9}, {%0,%1,%2,%3};"
                 : "+r"(d[0]), "+r"(d[1]), "+r"(d[2]), "+r"(d[3])
                 : "r"(a[0]), "r"(a[1]), "r"(a[2]), "r"(a[3]), "r"(b[0]), "r"(b[1]));
}

// ---------------------------------------------------------------------------
// Prep 1: keys = muw*softplus(sgw); knorm (exact fp32); int8 splits of k, mu.
// ---------------------------------------------------------------------------
__global__ __launch_bounds__(256) void prep_w(const float* __restrict__ muw,
                                              const float* __restrict__ sgw) {
    const int row = blockIdx.x;
    const int t = threadIdx.x;
    const size_t base = (size_t)row * IN_F + t * 8;
    float k[8], m[8];
    float4 m0 = *(const float4*)(muw + base);
    float4 m1 = *(const float4*)(muw + base + 4);
    float4 s0 = *(const float4*)(sgw + base);
    float4 s1 = *(const float4*)(sgw + base + 4);
    m[0]=m0.x; m[1]=m0.y; m[2]=m0.z; m[3]=m0.w; m[4]=m1.x; m[5]=m1.y; m[6]=m1.z; m[7]=m1.w;
    float s[8] = {s0.x,s0.y,s0.z,s0.w,s1.x,s1.y,s1.z,s1.w};
    float ss = 0.0f;
    int k0q[8], k1q[8], m0q[8], m1q[8];
    #pragma unroll
    for (int j = 0; j < 8; j++) {
        k[j] = m[j] * softplus_f(s[j]); ss += k[j]*k[j];
        k0q[j] = q8(k[j] * 4096.0f);                              // 2^12
        k1q[j] = q8((k[j] - k0q[j] * 0.000244140625f) * 1048576.0f);  // resid * 2^20
        m0q[j] = q8(m[j] * 4096.0f);
        m1q[j] = q8((m[j] - m0q[j] * 0.000244140625f) * 1048576.0f);
    }
    *(uint2*)(g_k0 + base) = make_uint2(pack4(k0q[0],k0q[1],k0q[2],k0q[3]), pack4(k0q[4],k0q[5],k0q[6],k0q[7]));
    *(uint2*)(g_k1 + base) = make_uint2(pack4(k1q[0],k1q[1],k1q[2],k1q[3]), pack4(k1q[4],k1q[5],k1q[6],k1q[7]));
    *(uint2*)(g_m0 + base) = make_uint2(pack4(m0q[0],m0q[1],m0q[2],m0q[3]), pack4(m0q[4],m0q[5],m0q[6],m0q[7]));
    *(uint2*)(g_m1 + base) = make_uint2(pack4(m1q[0],m1q[1],m1q[2],m1q[3]), pack4(m1q[4],m1q[5],m1q[6],m1q[7]));
    __shared__ float red[256];
    red[t] = ss;
    __syncthreads();
    for (int st = 128; st > 0; st >>= 1) {
        if (t < st) red[t] += red[t + st];
        __syncthreads();
    }
    if (t == 0) g_knorm[row] = sqrtf(red[0]);
}

// ---------------------------------------------------------------------------
// Prep 2: xnorm (exact); int8 split of x.
// ---------------------------------------------------------------------------
__global__ __launch_bounds__(256) void prep_x(const float* __restrict__ x) {
    const int row = blockIdx.x;
    const int t = threadIdx.x;
    const size_t base = (size_t)row * IN_F + t * 8;
    float4 v0 = *(const float4*)(x + base);
    float4 v1 = *(const float4*)(x + base + 4);
    float v[8] = {v0.x,v0.y,v0.z,v0.w,v1.x,v1.y,v1.z,v1.w};
    float ss = 0.0f;
    int x0q[8], x1q[8];
    #pragma unroll
    for (int j = 0; j < 8; j++) {
        ss += v[j]*v[j];
        x0q[j] = q8(v[j] * 16.0f);                          // 2^4
        x1q[j] = q8((v[j] - x0q[j] * 0.0625f) * 4096.0f);   // resid * 2^12
    }
    *(uint2*)(g_x0 + base) = make_uint2(pack4(x0q[0],x0q[1],x0q[2],x0q[3]), pack4(x0q[4],x0q[5],x0q[6],x0q[7]));
    *(uint2*)(g_x1 + base) = make_uint2(pack4(x1q[0],x1q[1],x1q[2],x1q[3]), pack4(x1q[4],x1q[5],x1q[6],x1q[7]));
    __shared__ float red[256];
    red[t] = ss;
    __syncthreads();
    for (int st = 128; st > 0; st >>= 1) {
        if (t < st) red[t] += red[t + st];
        __syncthreads();
    }
    if (t == 0) g_xnorm[row] = sqrtf(red[0]);
}

// ---------------------------------------------------------------------------
// Main int8 kernel: CTA 128x64, 8 warps (4M x 2N), warp tile 32x32.
// dots = 2^-16*(x0.k0) + 2^-24*(x0.k1 + x1.k0)
// comp = 2^-16*(x0.m0) + 2^-24*(x0.m1 + x1.m0)
// BK=64 (2 k-chunks of 32 per iter), 2-stage cp.async, ldmatrix b16 trick.
// ---------------------------------------------------------------------------
#define BM      128
#define BN      64
#define BK      64
#define ROWB    80                         // 64 int8 data + 16 pad; 16B-aligned, conflict-free
#define TILE_A  (BM * ROWB)                // 10240 B (x0 / x1)
#define TILE_BT (BN * ROWB)                // 5120 B  (k0 / k1 / m0 / m1)
#define STAGE_B (2 * TILE_A + 4 * TILE_BT) // 40960 B
#define NIT     (IN_F / BK)                // 32
// mainloop: 2 stages = 81920; epilogue reuse = 65536. max -> 81920.
#define SMEM_SZ 81920

__global__ __launch_bounds__(256, 1)
void moie_imma_kernel(const float* __restrict__ gate,
                      const float* __restrict__ bias,
                      float* __restrict__ out) {
    extern __shared__ char smem[];
    const uint32_t sbase = smem_u32(smem);
    const int tid  = threadIdx.x;
    const int warp = tid >> 5;
    const int lane = tid & 31;
    const int wm   = warp >> 1;          // 0..3 (M, 32 rows)
    const int wn   = warp & 1;           // 0..1 (N, 32 cols)
    const int mBase = blockIdx.y * BM;
    const int nBase = blockIdx.x * BN;

    int accDA[2][4][4], accDB[2][4][4];   // dots hi / lo-scale accumulators
    int accCA[2][4][4], accCB[2][4][4];   // comp hi / lo-scale
    #pragma unroll
    for (int i = 0; i < 2; i++)
        #pragma unroll
        for (int j = 0; j < 4; j++)
            #pragma unroll
            for (int q = 0; q < 4; q++) {
                accDA[i][j][q] = 0; accDB[i][j][q] = 0;
                accCA[i][j][q] = 0; accCB[i][j][q] = 0;
            }

    // ldmatrix per-lane byte offsets (verified against s8 m16n8k32 fragment layout)
    const uint32_t aOff = (uint32_t)(lane & 15) * ROWB + (uint32_t)(lane >> 4) * 16;
    const uint32_t bOff = (uint32_t)((lane & 7) | ((lane & 16) >> 1)) * ROWB + (uint32_t)((lane >> 3) & 1) * 16;

    // stage layout: [x0][x1][k0][k1][m0][m1], rows of 64 int8 (+16B pad)
    auto load_stage = [&](int slot, int it) {
        const uint32_t sb = sbase + (uint32_t)slot * STAGE_B;
        const int k0g = it * BK;
        // x0, x1: 128 rows x 4 chunks = 512 cp16 -> 2/thread each
        #pragma unroll
        for (int h = 0; h < 2; ++h) {
            const int8_t* gp = h ? g_x1 : g_x0;
            const uint32_t tb = sb + h * TILE_A;
            #pragma unroll
            for (int t = 0; t < 2; ++t) {
                const int v   = tid + t * 256;      // 0..511
                const int row = v >> 2;
                const int c16 = v & 3;
                cp16(tb + row * ROWB + c16 * 16,
                     gp + (size_t)(mBase + row) * IN_F + k0g + c16 * 16);
            }
        }
        // k0,k1,m0,m1: 64 rows x 4 chunks = 256 cp16 -> 1/thread each
        {
            const int row = tid >> 2;
            const int c16 = tid & 3;
            const uint32_t off = row * ROWB + c16 * 16;
            const size_t gof = (size_t)(nBase + row) * IN_F + k0g + c16 * 16;
            cp16(sb + 2 * TILE_A + 0 * TILE_BT + off, g_k0 + gof);
            cp16(sb + 2 * TILE_A + 1 * TILE_BT + off, g_k1 + gof);
            cp16(sb + 2 * TILE_A + 2 * TILE_BT + off, g_m0 + gof);
            cp16(sb + 2 * TILE_A + 3 * TILE_BT + off, g_m1 + gof);
        }
    };

    load_stage(0, 0); CP_COMMIT();

    for (int it = 0; it < NIT; ++it) {
        if (it + 1 < NIT) { load_stage((it + 1) & 1, it + 1); CP_COMMIT(); CP_WAIT1(); }
        else              { CP_WAIT0(); }
        __syncthreads();

        const uint32_t st  = sbase + (uint32_t)(it & 1) * STAGE_B;
        const uint32_t Ax0 = st;
        const uint32_t Ax1 = st + TILE_A;
        const uint32_t Bk0 = st + 2 * TILE_A;
        const uint32_t Bk1 = Bk0 + TILE_BT;
        const uint32_t Bm0 = Bk1 + TILE_BT;
        const uint32_t Bm1 = Bm0 + TILE_BT;
        const uint32_t aWarp = (uint32_t)(wm * 32) * ROWB;
        const uint32_t bWarp = (uint32_t)(wn * 32) * ROWB;

        #pragma unroll
        for (int ks = 0; ks < 2; ++ks) {            // two k32 chunks per iter
            const uint32_t kB = ks * 32;
            // ---- operands ----
            uint32_t a0[2][4], a1[2][4];
            #pragma unroll
            for (int mi = 0; mi < 2; ++mi) {
                ldsm_x4(a0[mi], Ax0 + aWarp + (uint32_t)(mi * 16) * ROWB + kB + aOff);
                ldsm_x4(a1[mi], Ax1 + aWarp + (uint32_t)(mi * 16) * ROWB + kB + aOff);
            }
            uint32_t bk0[4][2], bk1[4][2], bm0[4][2], bm1[4][2];
            #pragma unroll
            for (int nt = 0; nt < 2; ++nt) {
                uint32_t r[4];
                ldsm_x4(r, Bk0 + bWarp + (uint32_t)(nt * 16) * ROWB + kB + bOff);
                bk0[nt*2][0]=r[0]; bk0[nt*2][1]=r[1]; bk0[nt*2+1][0]=r[2]; bk0[nt*2+1][1]=r[3];
                ldsm_x4(r, Bk1 + bWarp + (uint32_t)(nt * 16) * ROWB + kB + bOff);
                bk1[nt*2][0]=r[0]; bk1[nt*2][1]=r[1]; bk1[nt*2+1][0]=r[2]; bk1[nt*2+1][1]=r[3];
                ldsm_x4(r, Bm0 + bWarp + (uint32_t)(nt * 16) * ROWB + kB + bOff);
                bm0[nt*2][0]=r[0]; bm0[nt*2][1]=r[1]; bm0[nt*2+1][0]=r[2]; bm0[nt*2+1][1]=r[3];
                ldsm_x4(r, Bm1 + bWarp + (uint32_t)(nt * 16) * ROWB + kB + bOff);
                bm1[nt*2][0]=r[0]; bm1[nt*2][1]=r[1]; bm1[nt*2+1][0]=r[2]; bm1[nt*2+1][1]=r[3];
            }
            // ---- 48 MMAs in 6 groups of 8 independent accumulators ----
            #pragma unroll
            for (int mi = 0; mi < 2; ++mi)
                #pragma unroll
                for (int ni = 0; ni < 4; ++ni)
                    mma_s8(accDA[mi][ni], a0[mi], bk0[ni]);   // x0.k0
            #pragma unroll
            for (int mi = 0; mi < 2; ++mi)
                #pragma unroll
                for (int ni = 0; ni < 4; ++ni)
                    mma_s8(accCA[mi][ni], a0[mi], bm0[ni]);   // x0.m0
            #pragma unroll
            for (int mi = 0; mi < 2; ++mi)
                #pragma unroll
                for (int ni = 0; ni < 4; ++ni)
                    mma_s8(accDB[mi][ni], a0[mi], bk1[ni]);   // x0.k1
            #pragma unroll
            for (int mi = 0; mi < 2; ++mi)
                #pragma unroll
                for (int ni = 0; ni < 4; ++ni)
                    mma_s8(accCB[mi][ni], a0[mi], bm1[ni]);   // x0.m1
            #pragma unroll
            for (int mi = 0; mi < 2; ++mi)
                #pragma unroll
                for (int ni = 0; ni < 4; ++ni)
                    mma_s8(accDB[mi][ni], a1[mi], bk0[ni]);   // x1.k0 (same scale)
            #pragma unroll
            for (int mi = 0; mi < 2; ++mi)
                #pragma unroll
                for (int ni = 0; ni < 4; ++ni)
                    mma_s8(accCB[mi][ni], a1[mi], bm0[ni]);   // x1.m0 (same scale)
        }
        __syncthreads();   // all warps done with slot (it&1) before refill
    }

    // ---- epilogue: combine scales, frags -> SMEM, fused scalar pass ----
    const float S_HI = 1.52587890625e-5f;        // 2^-16
    const float S_LO = 5.9604644775390625e-8f;   // 2^-24
    float* sD = (float*)smem;            // 128x64 dots  (32768 B)
    float* sC = sD + BM * BN;            // 128x64 comp  (total 65536 B)
    {
        const int r0 = wm * 32 + (lane >> 2);
        const int c0 = wn * 32 + (lane & 3) * 2;
        #pragma unroll
        for (int mi = 0; mi < 2; ++mi)
            #pragma unroll
            for (int ni = 0; ni < 4; ++ni) {
                const int r = r0 + mi * 16;
                const int c = c0 + ni * 8;
                float d0 = (float)accDA[mi][ni][0] * S_HI + (float)accDB[mi][ni][0] * S_LO;
                float d1 = (float)accDA[mi][ni][1] * S_HI + (float)accDB[mi][ni][1] * S_LO;
                float d2 = (float)accDA[mi][ni][2] * S_HI + (float)accDB[mi][ni][2] * S_LO;
                float d3 = (float)accDA[mi][ni][3] * S_HI + (float)accDB[mi][ni][3] * S_LO;
                float c0f = (float)accCA[mi][ni][0] * S_HI + (float)accCB[mi][ni][0] * S_LO;
                float c1f = (float)accCA[mi][ni][1] * S_HI + (float)accCB[mi][ni][1] * S_LO;
                float c2f = (float)accCA[mi][ni][2] * S_HI + (float)accCB[mi][ni][2] * S_LO;
                float c3f = (float)accCA[mi][ni][3] * S_HI + (float)accCB[mi][ni][3] * S_LO;
                *(float2*)(sD + r * BN + c)       = make_float2(d0, d1);
                *(float2*)(sD + (r + 8) * BN + c) = make_float2(d2, d3);
                *(float2*)(sC + r * BN + c)       = make_float2(c0f, c1f);
                *(float2*)(sC + (r + 8) * BN + c) = make_float2(c2f, c3f);
            }
    }
    __syncthreads();

    const size_t NO = (size_t)NROWS * OUT_F;
    #pragma unroll
    for (int e = 0; e < 8; ++e) {
        const int lin = e * 256 + tid;       // float4 slot, 0..2047
        const int row = lin >> 4;            // 0..127
        const int c4  = (lin & 15) * 4;      // 0..60
        const int m   = mBase + row;
        const float xn = g_xnorm[m];
        float4 d = *(float4*)(sD + row * BN + c4);
        float4 c = *(float4*)(sC + row * BN + c4);
        float sc[4], mk[4];
        const float* dv = &d.x;
        const float* cv = &c.x;
        #pragma unroll
        for (int j = 0; j < 4; ++j) {
            const int n = nBase + c4 + j;
            const float score = dv[j] / fmaxf(xn * g_knorm[n], 1e-8f);
            const float w = fmaxf(score - gate[n], 0.0f);
            sc[j] = score;
            mk[j] = (cv[j] + bias[n]) * w;
        }
        float4 sc4 = make_float4(sc[0], sc[1], sc[2], sc[3]);
        float4 mk4 = make_float4(mk[0], mk[1], mk[2], mk[3]);
        const size_t idx = (size_t)m * OUT_F + nBase + c4;
        *(float4*)(out + idx)          = mk4;   // output
        *(float4*)(out + NO + idx)     = sc4;   // scores
        *(float4*)(out + 2 * NO + idx) = mk4;   // masked
    }
}

// ---------------------------------------------------------------------------
extern "C" void kernel_launch(void* const* d_in, const int* in_sizes, int n_in,
                              void* d_out, int out_size) {
    const float* x    = (const float*)d_in[0];
    const float* muw  = (const float*)d_in[1];
    const float* sgw  = (const float*)d_in[2];
    const float* gate = (const float*)d_in[3];
    const float* bias = (const float*)d_in[4];
    float* out = (float*)d_out;

    cudaFuncSetAttribute(moie_imma_kernel, cudaFuncAttributeMaxDynamicSharedMemorySize, SMEM_SZ);

    prep_w<<<OUT_F, 256>>>(muw, sgw);
    prep_x<<<NROWS, 256>>>(x);
    dim3 grid(OUT_F / BN, NROWS / BM);
    moie_imma_kernel<<<grid, 256, SMEM_SZ>>>(gate, bias, out);
}

// round 16
// speedup vs baseline: 5.0604x; 5.0604x over previous
#include <cuda_runtime.h>
#include <cuda_fp16.h>
#include <math.h>
#include <stdint.h>

#define IN_F  2048
#define OUT_F 2048
#define NROWS 8192   // 4 * 2048

// ---------------------------------------------------------------------------
// Scratch (__device__ globals; no runtime allocation allowed)
// ---------------------------------------------------------------------------
__device__ __align__(16) __half g_xh[(size_t)NROWS * IN_F];
__device__ __align__(16) __half g_xl[(size_t)NROWS * IN_F];
__device__ __align__(16) __half g_kh[(size_t)OUT_F * IN_F];
__device__ float g_knorm[OUT_F];
__device__ float g_xnorm[NROWS];

__device__ __forceinline__ float softplus_f(float x) {
    return fmaxf(x, 0.0f) + log1pf(expf(-fabsf(x)));
}

__device__ __forceinline__ void cp16(uint32_t sa, const void* gp) {
    asm volatile("cp.async.cg.shared.global [%0], [%1], 16;"
                 :: "r"(sa), "l"(__cvta_generic_to_global(gp)) : "memory");
}
#define CP_COMMIT() asm volatile("cp.async.commit_group;" ::: "memory")
#define CP_WAIT1()  asm volatile("cp.async.wait_group 1;" ::: "memory")
#define CP_WAIT0()  asm volatile("cp.async.wait_group 0;" ::: "memory")

__device__ __forceinline__ uint32_t smem_u32(const void* p) {
    uint32_t a;
    asm("{ .reg .u64 t; cvta.to.shared.u64 t, %1; cvt.u32.u64 %0, t; }" : "=r"(a) : "l"(p));
    return a;
}

__device__ __forceinline__ void ldsm_x4(uint32_t* r, uint32_t addr) {
    asm volatile("ldmatrix.sync.aligned.m8n8.x4.shared.b16 {%0,%1,%2,%3}, [%4];"
                 : "=r"(r[0]), "=r"(r[1]), "=r"(r[2]), "=r"(r[3]) : "r"(addr));
}

__device__ __forceinline__ void mma16816(float* d, const uint32_t* a, const uint32_t* b) {
    asm volatile("mma.sync.aligned.m16n8k16.row.col.f32.f16.f16.f32 "
                 "{%0,%1,%2,%3}, {%4,%5,%6,%7}, {%8,%9}, {%0,%1,%2,%3};"
                 : "+f"(d[0]), "+f"(d[1]), "+f"(d[2]), "+f"(d[3])
                 : "r"(a[0]), "r"(a[1]), "r"(a[2]), "r"(a[3]), "r"(b[0]), "r"(b[1]));
}

// ---------------------------------------------------------------------------
// Prep 1: keys = muw*softplus(sgw); knorm (exact fp32); store fp16 kh only.
// ---------------------------------------------------------------------------
__global__ __launch_bounds__(256) void prep_w(const float* __restrict__ muw,
                                              const float* __restrict__ sgw) {
    const int row = blockIdx.x;
    const int t = threadIdx.x;
    const size_t base = (size_t)row * IN_F + t * 8;
    float k[8], m[8];
    float4 m0 = *(const float4*)(muw + base);
    float4 m1 = *(const float4*)(muw + base + 4);
    float4 s0 = *(const float4*)(sgw + base);
    float4 s1 = *(const float4*)(sgw + base + 4);
    m[0]=m0.x; m[1]=m0.y; m[2]=m0.z; m[3]=m0.w; m[4]=m1.x; m[5]=m1.y; m[6]=m1.z; m[7]=m1.w;
    float s[8] = {s0.x,s0.y,s0.z,s0.w,s1.x,s1.y,s1.z,s1.w};
    float ss = 0.0f;
    #pragma unroll
    for (int j = 0; j < 8; j++) { k[j] = m[j] * softplus_f(s[j]); ss += k[j]*k[j]; }
    #pragma unroll
    for (int j = 0; j < 8; j += 2)
        *(__half2*)(g_kh + base + j) = __half2(__float2half(k[j]), __float2half(k[j+1]));
    __shared__ float red[256];
    red[t] = ss;
    __syncthreads();
    for (int st = 128; st > 0; st >>= 1) {
        if (t < st) red[t] += red[t + st];
        __syncthreads();
    }
    if (t == 0) g_knorm[row] = sqrtf(red[0]);
}

// ---------------------------------------------------------------------------
// Prep 2: xnorm (exact); fp16 hi/lo split of x.
// ---------------------------------------------------------------------------
__global__ __launch_bounds__(256) void prep_x(const float* __restrict__ x) {
    const int row = blockIdx.x;
    const int t = threadIdx.x;
    const size_t base = (size_t)row * IN_F + t * 8;
    float4 v0 = *(const float4*)(x + base);
    float4 v1 = *(const float4*)(x + base + 4);
    float v[8] = {v0.x,v0.y,v0.z,v0.w,v1.x,v1.y,v1.z,v1.w};
    float ss = 0.0f;
    #pragma unroll
    for (int j = 0; j < 8; j++) ss += v[j]*v[j];
    #pragma unroll
    for (int j = 0; j < 8; j += 2) {
        __half h0 = __float2half(v[j]),   h1 = __float2half(v[j+1]);
        __half l0 = __float2half(v[j]   - __half2float(h0));
        __half l1 = __float2half(v[j+1] - __half2float(h1));
        *(__half2*)(g_xh + base + j) = __half2(h0, h1);
        *(__half2*)(g_xl + base + j) = __half2(l0, l1);
    }
    __shared__ float red[256];
    red[t] = ss;
    __syncthreads();
    for (int st = 128; st > 0; st >>= 1) {
        if (t < st) red[t] += red[t + st];
        __syncthreads();
    }
    if (t == 0) g_xnorm[row] = sqrtf(red[0]);
}

// ---------------------------------------------------------------------------
// Main kernel: dots GEMM only (scores). CTA 128x64, 8 warps (4M x 2N),
// warp tile 32x32, 2 CTAs/SM, 2-stage cp.async.
//   dots = xh*kh + xl*kh = x*kh   (exact x; err only from fp16 kh)
// masked = (comp+bias)*relu(score-gate) is ~always 0 because gate=0.1 and
// scores ~ N(0, 1/2048) (4.5 sigma). The rare score>gate entries trigger an
// exact fp32 fallback dot product against x and muw in global memory.
// ---------------------------------------------------------------------------
#define BM      128
#define BN      64
#define BK      32
#define LDT     40                        // padded row len (fp16); conflict-free
#define TILE_A  (BM * LDT * 2)            // 10240 bytes (xh / xl)
#define TILE_BT (BN * LDT * 2)            // 5120 bytes  (kh)
#define STAGE_B (2 * TILE_A + TILE_BT)    // 25600 bytes
#define NIT     (IN_F / BK)               // 64
// mainloop: 2 stages = 51200; epilogue: 128x64 fp32 = 32768. max -> 51200.
#define SMEM_SZ 51200

__global__ __launch_bounds__(256, 2)
void moie_mma_kernel(const float* __restrict__ x,
                     const float* __restrict__ muw,
                     const float* __restrict__ gate,
                     const float* __restrict__ bias,
                     float* __restrict__ out) {
    extern __shared__ char smem[];
    const uint32_t sbase = smem_u32(smem);
    const int tid  = threadIdx.x;
    const int warp = tid >> 5;
    const int lane = tid & 31;
    const int wm   = warp >> 1;          // 0..3 (M, 32 rows)
    const int wn   = warp & 1;           // 0..1 (N, 32 cols)
    const int mBase = blockIdx.y * BM;
    const int nBase = blockIdx.x * BN;

    float accD[2][4][4];   // dots: 2 m16 x 4 n8
    #pragma unroll
    for (int i = 0; i < 2; i++)
        #pragma unroll
        for (int j = 0; j < 4; j++)
            #pragma unroll
            for (int q = 0; q < 4; q++) accD[i][j][q] = 0.0f;

    const uint32_t aOff = ((lane & 15) * LDT + (lane >> 4) * 8) * 2;
    const uint32_t bOff = (((lane & 7) | ((lane & 16) >> 1)) * LDT + ((lane >> 3) & 1) * 8) * 2;

    // stage layout: [xh(10240)][xl(10240)][kh(5120)]
    auto load_stage = [&](int slot, int it) {
        const uint32_t sb = sbase + (uint32_t)slot * STAGE_B;
        const int k0 = it * BK;
        #pragma unroll
        for (int h = 0; h < 2; ++h) {
            const __half* gp = h ? g_xl : g_xh;
            const uint32_t tb = sb + h * TILE_A;
            #pragma unroll
            for (int t = 0; t < 2; ++t) {
                const int v   = tid + t * 256;      // 0..511
                const int row = v >> 2;
                const int c16 = v & 3;
                cp16(tb + row * (LDT * 2) + c16 * 16,
                     gp + (size_t)(mBase + row) * IN_F + k0 + c16 * 8);
            }
        }
        {
            const int row = tid >> 2;
            const int c16 = tid & 3;
            cp16(sb + 2 * TILE_A + row * (LDT * 2) + c16 * 16,
                 g_kh + (size_t)(nBase + row) * IN_F + k0 + c16 * 8);
        }
    };

    load_stage(0, 0); CP_COMMIT();

    for (int it = 0; it < NIT; ++it) {
        if (it + 1 < NIT) { load_stage((it + 1) & 1, it + 1); CP_COMMIT(); CP_WAIT1(); }
        else              { CP_WAIT0(); }
        __syncthreads();

        const uint32_t st  = sbase + (uint32_t)(it & 1) * STAGE_B;
        const uint32_t Axh = st;
        const uint32_t Axl = st + TILE_A;
        const uint32_t Bkh = st + 2 * TILE_A;
        const uint32_t aWarp = (uint32_t)(wm * 32) * (LDT * 2);
        const uint32_t bWarp = (uint32_t)(wn * 32) * (LDT * 2);

        #pragma unroll
        for (int ks = 0; ks < BK / 16; ++ks) {
            const uint32_t kB = ks * 32;
            uint32_t ah[2][4], al[2][4];
            #pragma unroll
            for (int mi = 0; mi < 2; ++mi) {
                ldsm_x4(ah[mi], Axh + aWarp + (uint32_t)(mi * 16) * (LDT * 2) + kB + aOff);
                ldsm_x4(al[mi], Axl + aWarp + (uint32_t)(mi * 16) * (LDT * 2) + kB + aOff);
            }
            uint32_t bk[4][2];
            #pragma unroll
            for (int nt = 0; nt < 2; ++nt) {
                uint32_t r[4];
                ldsm_x4(r, Bkh + bWarp + (uint32_t)(nt * 16) * (LDT * 2) + kB + bOff);
                bk[nt*2][0] = r[0]; bk[nt*2][1] = r[1]; bk[nt*2+1][0] = r[2]; bk[nt*2+1][1] = r[3];
            }
            // 16 MMAs in 2 groups of 8 independent accumulators
            #pragma unroll
            for (int mi = 0; mi < 2; ++mi)
                #pragma unroll
                for (int ni = 0; ni < 4; ++ni)
                    mma16816(accD[mi][ni], ah[mi], bk[ni]);
            #pragma unroll
            for (int mi = 0; mi < 2; ++mi)
                #pragma unroll
                for (int ni = 0; ni < 4; ++ni)
                    mma16816(accD[mi][ni], al[mi], bk[ni]);
        }
        __syncthreads();
    }

    // ---- epilogue: dots -> SMEM, then scores + sparse masked ----
    float* sD = (float*)smem;            // 128x64 dots (32768 B)
    {
        const int r0 = wm * 32 + (lane >> 2);
        const int c0 = wn * 32 + (lane & 3) * 2;
        #pragma unroll
        for (int mi = 0; mi < 2; ++mi)
            #pragma unroll
            for (int ni = 0; ni < 4; ++ni) {
                const int r = r0 + mi * 16;
                const int c = c0 + ni * 8;
                *(float2*)(sD + r * BN + c)       = make_float2(accD[mi][ni][0], accD[mi][ni][1]);
                *(float2*)(sD + (r + 8) * BN + c) = make_float2(accD[mi][ni][2], accD[mi][ni][3]);
            }
    }
    __syncthreads();

    const size_t NO = (size_t)NROWS * OUT_F;
    #pragma unroll
    for (int e = 0; e < 8; ++e) {
        const int lin = e * 256 + tid;       // float4 slot, 0..2047
        const int row = lin >> 4;            // 0..127
        const int c4  = (lin & 15) * 4;      // 0..60
        const int m   = mBase + row;
        const float xn = g_xnorm[m];
        float4 d = *(float4*)(sD + row * BN + c4);
        float sc[4], mk[4];
        const float* dv = &d.x;
        #pragma unroll
        for (int j = 0; j < 4; ++j) {
            const int n = nBase + c4 + j;
            const float score = dv[j] / fmaxf(xn * g_knorm[n], 1e-8f);
            sc[j] = score;
            const float gt = gate[n];
            if (score > gt) {
                // rare path (~3e-6 density): exact fp32 comp
                float acc = 0.0f;
                const float4* xp = (const float4*)(x + (size_t)m * IN_F);
                const float4* wp = (const float4*)(muw + (size_t)n * IN_F);
                #pragma unroll 4
                for (int kk = 0; kk < IN_F / 4; ++kk) {
                    float4 a = xp[kk], b = wp[kk];
                    acc += a.x*b.x + a.y*b.y + a.z*b.z + a.w*b.w;
                }
                mk[j] = (acc + bias[n]) * (score - gt);
            } else {
                mk[j] = 0.0f;
            }
        }
        float4 sc4 = make_float4(sc[0], sc[1], sc[2], sc[3]);
        float4 mk4 = make_float4(mk[0], mk[1], mk[2], mk[3]);
        const size_t idx = (size_t)m * OUT_F + nBase + c4;
        *(float4*)(out + idx)          = mk4;   // output
        *(float4*)(out + NO + idx)     = sc4;   // scores
        *(float4*)(out + 2 * NO + idx) = mk4;   // masked
    }
}

// ---------------------------------------------------------------------------
extern "C" void kernel_launch(void* const* d_in, const int* in_sizes, int n_in,
                              void* d_out, int out_size) {
    const float* x    = (const float*)d_in[0];
    const float* muw  = (const float*)d_in[1];
    const float* sgw  = (const float*)d_in[2];
    const float* gate = (const float*)d_in[3];
    const float* bias = (const float*)d_in[4];
    float* out = (float*)d_out;

    cudaFuncSetAttribute(moie_mma_kernel, cudaFuncAttributeMaxDynamicSharedMemorySize, SMEM_SZ);

    prep_w<<<OUT_F, 256>>>(muw, sgw);
    prep_x<<<NROWS, 256>>>(x);
    dim3 grid(OUT_F / BN, NROWS / BM);
    moie_mma_kernel<<<grid, 256, SMEM_SZ>>>(x, muw, gate, bias, out);
}

// round 17
// speedup vs baseline: 6.2289x; 1.2309x over previous
#include <cuda_runtime.h>
#include <cuda_fp16.h>
#include <math.h>
#include <stdint.h>

#define IN_F  2048
#define OUT_F 2048
#define NROWS 8192   // 4 * 2048

// ---------------------------------------------------------------------------
// Scratch (__device__ globals; no runtime allocation allowed)
// ---------------------------------------------------------------------------
__device__ __align__(16) __half g_xh[(size_t)NROWS * IN_F];
__device__ __align__(16) __half g_xl[(size_t)NROWS * IN_F];
__device__ __align__(16) __half g_kh[(size_t)OUT_F * IN_F];
__device__ float g_knorm[OUT_F];
__device__ float g_xnorm[NROWS];

__device__ __forceinline__ float softplus_f(float x) {
    return fmaxf(x, 0.0f) + log1pf(expf(-fabsf(x)));
}

__device__ __forceinline__ void cp16(uint32_t sa, const void* gp) {
    asm volatile("cp.async.cg.shared.global [%0], [%1], 16;"
                 :: "r"(sa), "l"(__cvta_generic_to_global(gp)) : "memory");
}
#define CP_COMMIT() asm volatile("cp.async.commit_group;" ::: "memory")
#define CP_WAIT1()  asm volatile("cp.async.wait_group 1;" ::: "memory")
#define CP_WAIT0()  asm volatile("cp.async.wait_group 0;" ::: "memory")

__device__ __forceinline__ uint32_t smem_u32(const void* p) {
    uint32_t a;
    asm("{ .reg .u64 t; cvta.to.shared.u64 t, %1; cvt.u32.u64 %0, t; }" : "=r"(a) : "l"(p));
    return a;
}

__device__ __forceinline__ void ldsm_x4(uint32_t* r, uint32_t addr) {
    asm volatile("ldmatrix.sync.aligned.m8n8.x4.shared.b16 {%0,%1,%2,%3}, [%4];"
                 : "=r"(r[0]), "=r"(r[1]), "=r"(r[2]), "=r"(r[3]) : "r"(addr));
}

__device__ __forceinline__ void mma16816(float* d, const uint32_t* a, const uint32_t* b) {
    asm volatile("mma.sync.aligned.m16n8k16.row.col.f32.f16.f16.f32 "
                 "{%0,%1,%2,%3}, {%4,%5,%6,%7}, {%8,%9}, {%0,%1,%2,%3};"
                 : "+f"(d[0]), "+f"(d[1]), "+f"(d[2]), "+f"(d[3])
                 : "r"(a[0]), "r"(a[1]), "r"(a[2]), "r"(a[3]), "r"(b[0]), "r"(b[1]));
}

// ---------------------------------------------------------------------------
// Prep 1: keys = muw*softplus(sgw); knorm (exact fp32); store fp16 kh only.
// ---------------------------------------------------------------------------
__global__ __launch_bounds__(256) void prep_w(const float* __restrict__ muw,
                                              const float* __restrict__ sgw) {
    const int row = blockIdx.x;
    const int t = threadIdx.x;
    const size_t base = (size_t)row * IN_F + t * 8;
    float k[8], m[8];
    float4 m0 = *(const float4*)(muw + base);
    float4 m1 = *(const float4*)(muw + base + 4);
    float4 s0 = *(const float4*)(sgw + base);
    float4 s1 = *(const float4*)(sgw + base + 4);
    m[0]=m0.x; m[1]=m0.y; m[2]=m0.z; m[3]=m0.w; m[4]=m1.x; m[5]=m1.y; m[6]=m1.z; m[7]=m1.w;
    float s[8] = {s0.x,s0.y,s0.z,s0.w,s1.x,s1.y,s1.z,s1.w};
    float ss = 0.0f;
    #pragma unroll
    for (int j = 0; j < 8; j++) { k[j] = m[j] * softplus_f(s[j]); ss += k[j]*k[j]; }
    #pragma unroll
    for (int j = 0; j < 8; j += 2)
        *(__half2*)(g_kh + base + j) = __half2(__float2half(k[j]), __float2half(k[j+1]));
    __shared__ float red[256];
    red[t] = ss;
    __syncthreads();
    for (int st = 128; st > 0; st >>= 1) {
        if (t < st) red[t] += red[t + st];
        __syncthreads();
    }
    if (t == 0) g_knorm[row] = sqrtf(red[0]);
}

// ---------------------------------------------------------------------------
// Prep 2: xnorm (exact); fp16 hi/lo split of x.
// ---------------------------------------------------------------------------
__global__ __launch_bounds__(256) void prep_x(const float* __restrict__ x) {
    const int row = blockIdx.x;
    const int t = threadIdx.x;
    const size_t base = (size_t)row * IN_F + t * 8;
    float4 v0 = *(const float4*)(x + base);
    float4 v1 = *(const float4*)(x + base + 4);
    float v[8] = {v0.x,v0.y,v0.z,v0.w,v1.x,v1.y,v1.z,v1.w};
    float ss = 0.0f;
    #pragma unroll
    for (int j = 0; j < 8; j++) ss += v[j]*v[j];
    #pragma unroll
    for (int j = 0; j < 8; j += 2) {
        __half h0 = __float2half(v[j]),   h1 = __float2half(v[j+1]);
        __half l0 = __float2half(v[j]   - __half2float(h0));
        __half l1 = __float2half(v[j+1] - __half2float(h1));
        *(__half2*)(g_xh + base + j) = __half2(h0, h1);
        *(__half2*)(g_xl + base + j) = __half2(l0, l1);
    }
    __shared__ float red[256];
    red[t] = ss;
    __syncthreads();
    for (int st = 128; st > 0; st >>= 1) {
        if (t < st) red[t] += red[t + st];
        __syncthreads();
    }
    if (t == 0) g_xnorm[row] = sqrtf(red[0]);
}

// ---------------------------------------------------------------------------
// Main kernel: dots GEMM only. CTA 128x128, 8 warps (4M x 2N), warp 32x64.
// 2 CTAs/SM, 2-stage cp.async.
//   dots = xh*kh + xl*kh = x*kh   (exact x; err only from fp16 kh)
// masked is ~always 0 (gate=0.1 vs scores ~ N(0,1/2048)); rare score>gate
// entries use an exact fp32 dot from global memory.
// ---------------------------------------------------------------------------
#define BM      128
#define BN      128
#define BK      32
#define LDT     40                        // padded row len (fp16); conflict-free
#define TILE_A  (BM * LDT * 2)            // 10240 bytes (xh / xl)
#define TILE_BT (BN * LDT * 2)            // 10240 bytes (kh, 128 rows)
#define STAGE_B (2 * TILE_A + TILE_BT)    // 30720 bytes
#define NIT     (IN_F / BK)               // 64
// mainloop: 2 stages = 61440; epilogue: 128x128 fp32 = 65536. max -> 65536.
#define SMEM_SZ 65536

__global__ __launch_bounds__(256, 2)
void moie_mma_kernel(const float* __restrict__ x,
                     const float* __restrict__ muw,
                     const float* __restrict__ gate,
                     const float* __restrict__ bias,
                     float* __restrict__ out) {
    extern __shared__ char smem[];
    const uint32_t sbase = smem_u32(smem);
    const int tid  = threadIdx.x;
    const int warp = tid >> 5;
    const int lane = tid & 31;
    const int wm   = warp >> 1;          // 0..3 (M, 32 rows)
    const int wn   = warp & 1;           // 0..1 (N, 64 cols)
    const int mBase = blockIdx.y * BM;
    const int nBase = blockIdx.x * BN;

    float accD[2][8][4];   // dots: 2 m16 x 8 n8
    #pragma unroll
    for (int i = 0; i < 2; i++)
        #pragma unroll
        for (int j = 0; j < 8; j++)
            #pragma unroll
            for (int q = 0; q < 4; q++) accD[i][j][q] = 0.0f;

    const uint32_t aOff = ((lane & 15) * LDT + (lane >> 4) * 8) * 2;
    const uint32_t bOff = (((lane & 7) | ((lane & 16) >> 1)) * LDT + ((lane >> 3) & 1) * 8) * 2;

    // stage layout: [xh(10240)][xl(10240)][kh(10240)]
    auto load_stage = [&](int slot, int it) {
        const uint32_t sb = sbase + (uint32_t)slot * STAGE_B;
        const int k0 = it * BK;
        #pragma unroll
        for (int h = 0; h < 2; ++h) {
            const __half* gp = h ? g_xl : g_xh;
            const uint32_t tb = sb + h * TILE_A;
            #pragma unroll
            for (int t = 0; t < 2; ++t) {
                const int v   = tid + t * 256;      // 0..511
                const int row = v >> 2;
                const int c16 = v & 3;
                cp16(tb + row * (LDT * 2) + c16 * 16,
                     gp + (size_t)(mBase + row) * IN_F + k0 + c16 * 8);
            }
        }
        {
            const uint32_t tb = sb + 2 * TILE_A;
            #pragma unroll
            for (int t = 0; t < 2; ++t) {
                const int v   = tid + t * 256;      // 0..511
                const int row = v >> 2;
                const int c16 = v & 3;
                cp16(tb + row * (LDT * 2) + c16 * 16,
                     g_kh + (size_t)(nBase + row) * IN_F + k0 + c16 * 8);
            }
        }
    };

    load_stage(0, 0); CP_COMMIT();

    for (int it = 0; it < NIT; ++it) {
        if (it + 1 < NIT) { load_stage((it + 1) & 1, it + 1); CP_COMMIT(); CP_WAIT1(); }
        else              { CP_WAIT0(); }
        __syncthreads();

        const uint32_t st  = sbase + (uint32_t)(it & 1) * STAGE_B;
        const uint32_t Axh = st;
        const uint32_t Axl = st + TILE_A;
        const uint32_t Bkh = st + 2 * TILE_A;
        const uint32_t aWarp = (uint32_t)(wm * 32) * (LDT * 2);
        const uint32_t bWarp = (uint32_t)(wn * 64) * (LDT * 2);

        #pragma unroll
        for (int ks = 0; ks < BK / 16; ++ks) {
            const uint32_t kB = ks * 32;
            uint32_t ah[2][4], al[2][4];
            #pragma unroll
            for (int mi = 0; mi < 2; ++mi) {
                ldsm_x4(ah[mi], Axh + aWarp + (uint32_t)(mi * 16) * (LDT * 2) + kB + aOff);
                ldsm_x4(al[mi], Axl + aWarp + (uint32_t)(mi * 16) * (LDT * 2) + kB + aOff);
            }
            uint32_t bk[8][2];
            #pragma unroll
            for (int nt = 0; nt < 4; ++nt) {
                uint32_t r[4];
                ldsm_x4(r, Bkh + bWarp + (uint32_t)(nt * 16) * (LDT * 2) + kB + bOff);
                bk[nt*2][0] = r[0]; bk[nt*2][1] = r[1]; bk[nt*2+1][0] = r[2]; bk[nt*2+1][1] = r[3];
            }
            // 32 MMAs in 2 groups of 16 independent accumulators
            #pragma unroll
            for (int mi = 0; mi < 2; ++mi)
                #pragma unroll
                for (int ni = 0; ni < 8; ++ni)
                    mma16816(accD[mi][ni], ah[mi], bk[ni]);
            #pragma unroll
            for (int mi = 0; mi < 2; ++mi)
                #pragma unroll
                for (int ni = 0; ni < 8; ++ni)
                    mma16816(accD[mi][ni], al[mi], bk[ni]);
        }
        __syncthreads();
    }

    // ---- epilogue: dots -> SMEM, then scores + sparse masked ----
    float* sD = (float*)smem;            // 128x128 dots (65536 B)
    {
        const int r0 = wm * 32 + (lane >> 2);
        const int c0 = wn * 64 + (lane & 3) * 2;
        #pragma unroll
        for (int mi = 0; mi < 2; ++mi)
            #pragma unroll
            for (int ni = 0; ni < 8; ++ni) {
                const int r = r0 + mi * 16;
                const int c = c0 + ni * 8;
                *(float2*)(sD + r * BN + c)       = make_float2(accD[mi][ni][0], accD[mi][ni][1]);
                *(float2*)(sD + (r + 8) * BN + c) = make_float2(accD[mi][ni][2], accD[mi][ni][3]);
            }
    }
    __syncthreads();

    const size_t NO = (size_t)NROWS * OUT_F;
    #pragma unroll
    for (int e = 0; e < 16; ++e) {
        const int lin = e * 256 + tid;       // float4 slot, 0..4095
        const int row = lin >> 5;            // 0..127
        const int c4  = (lin & 31) * 4;      // 0..124
        const int m   = mBase + row;
        const float xn = g_xnorm[m];
        float4 d = *(float4*)(sD + row * BN + c4);
        float sc[4], mk[4];
        const float* dv = &d.x;
        #pragma unroll
        for (int j = 0; j < 4; ++j) {
            const int n = nBase + c4 + j;
            const float score = dv[j] / fmaxf(xn * g_knorm[n], 1e-8f);
            sc[j] = score;
            const float gt = gate[n];
            if (score > gt) {
                // rare path (~3e-6 density): exact fp32 comp
                float acc = 0.0f;
                const float4* xp = (const float4*)(x + (size_t)m * IN_F);
                const float4* wp = (const float4*)(muw + (size_t)n * IN_F);
                #pragma unroll 4
                for (int kk = 0; kk < IN_F / 4; ++kk) {
                    float4 a = xp[kk], b = wp[kk];
                    acc += a.x*b.x + a.y*b.y + a.z*b.z + a.w*b.w;
                }
                mk[j] = (acc + bias[n]) * (score - gt);
            } else {
                mk[j] = 0.0f;
            }
        }
        float4 sc4 = make_float4(sc[0], sc[1], sc[2], sc[3]);
        float4 mk4 = make_float4(mk[0], mk[1], mk[2], mk[3]);
        const size_t idx = (size_t)m * OUT_F + nBase + c4;
        *(float4*)(out + idx)          = mk4;   // output
        *(float4*)(out + NO + idx)     = sc4;   // scores
        *(float4*)(out + 2 * NO + idx) = mk4;   // masked
    }
}

// ---------------------------------------------------------------------------
extern "C" void kernel_launch(void* const* d_in, const int* in_sizes, int n_in,
                              void* d_out, int out_size) {
    const float* x    = (const float*)d_in[0];
    const float* muw  = (const float*)d_in[1];
    const float* sgw  = (const float*)d_in[2];
    const float* gate = (const float*)d_in[3];
    const float* bias = (const float*)d_in[4];
    float* out = (float*)d_out;

    cudaFuncSetAttribute(moie_mma_kernel, cudaFuncAttributeMaxDynamicSharedMemorySize, SMEM_SZ);

    prep_w<<<OUT_F, 256>>>(muw, sgw);
    prep_x<<<NROWS, 256>>>(x);
    dim3 grid(OUT_F / BN, NROWS / BM);
    moie_mma_kernel<<<grid, 256, SMEM_SZ>>>(x, muw, gate, bias, out);
}